// round 14
// baseline (speedup 1.0000x reference)
#include <cuda_runtime.h>
#include <cuda_fp16.h>
#include <cstdint>
#include <math.h>

#define NTOK 32768
#define CDIM 1024
#define NHEAD 16
#define HD 64

// ---------------- scratch ---------------------------------------------------
__device__ __half g_h16[NTOK * CDIM];       // attn out fp16
__device__ __half g_x16[NTOK * CDIM];       // x fp16
__device__ __half g_w1p[CDIM * 3 * CDIM];   // Wqkv pair-packed
__device__ __half g_w2p[CDIM * CDIM];       // Wout pair-packed
// fp16 splits for attention (V has no lo part — linear path, fp16 rounding ok)
__device__ __half g_qh[NTOK * CDIM];
__device__ __half g_ql[NTOK * CDIM];
__device__ __half g_kh[NTOK * CDIM];
__device__ __half g_kl[NTOK * CDIM];
__device__ __half g_vh[NTOK * CDIM];

// ---------------- helpers ---------------------------------------------------
__device__ __forceinline__ void mma_f16(float* d, const uint32_t* a, const uint32_t* b) {
    asm volatile(
        "mma.sync.aligned.m16n8k16.row.col.f32.f16.f16.f32 "
        "{%0,%1,%2,%3}, {%4,%5,%6,%7}, {%8,%9}, {%0,%1,%2,%3};\n"
        : "+f"(d[0]), "+f"(d[1]), "+f"(d[2]), "+f"(d[3])
        : "r"(a[0]), "r"(a[1]), "r"(a[2]), "r"(a[3]), "r"(b[0]), "r"(b[1]));
}

__device__ __forceinline__ void cpasync16(uint32_t dst, const void* src) {
    asm volatile("cp.async.cg.shared.global [%0], [%1], 16;" :: "r"(dst), "l"(src));
}
#define CP_COMMIT() asm volatile("cp.async.commit_group;")

#define LDMX4(r0, r1, r2, r3, addr) \
    asm volatile("ldmatrix.sync.aligned.m8n8.x4.shared.b16 {%0,%1,%2,%3}, [%4];" \
        : "=r"(r0), "=r"(r1), "=r"(r2), "=r"(r3) : "r"(addr))

#define LDMX4T(r0, r1, r2, r3, addr) \
    asm volatile("ldmatrix.sync.aligned.m8n8.x4.trans.shared.b16 {%0,%1,%2,%3}, [%4];" \
        : "=r"(r0), "=r"(r1), "=r"(r2), "=r"(r3) : "r"(addr))

__device__ __forceinline__ uint32_t packh2(float a, float b) {
    __half2 h = __floats2half2_rn(a, b);
    return *(uint32_t*)&h;
}

// ---------------- GEMM (fp16 MMA, 4-stage cp.async, ldmatrix A) -------------
// FUSED=true: epilogue does RMSNorm+RoPE+fp16-splits in place of fp32 store.
#define APADH 40
#define BPADU 136
#define A_TILE_B (128 * APADH * 2)
#define B_TILE_B (16 * BPADU * 4)
#define STAGE_B (A_TILE_B + B_TILE_B)
#define GEMM_SMEM (4 * STAGE_B)

template <bool FUSED>
__global__ __launch_bounds__(256, 2)
void gemm_f16_kernel(const __half* __restrict__ A, const __half* __restrict__ Bp,
                     const float* __restrict__ bias, float* __restrict__ Cmat,
                     const int* __restrict__ coords,
                     const float* __restrict__ gq, const float* __restrict__ gk,
                     __half* __restrict__ qh, __half* __restrict__ ql,
                     __half* __restrict__ kh, __half* __restrict__ kl,
                     __half* __restrict__ vh,
                     int M, int N, int K)
{
    extern __shared__ char sgm[];
    const uint32_t sbase = (uint32_t)__cvta_generic_to_shared(sgm);
    const int tid  = threadIdx.x;
    const int lane = tid & 31, warp = tid >> 5;
    const int g    = lane >> 2, tg = lane & 3;
    const int wr   = warp >> 2, wc = warp & 3;
    const int rowBase = blockIdx.y * 128;
    const int colBase = blockIdx.x * 128;
    const int NT = K >> 5;
    const uint32_t* Bp32 = (const uint32_t*)Bp;
    const int Nu = N;

    float acc[4][4][4];
#pragma unroll
    for (int mi = 0; mi < 4; mi++)
#pragma unroll
        for (int ni = 0; ni < 4; ni++)
#pragma unroll
            for (int q = 0; q < 4; q++) acc[mi][ni][q] = 0.f;

    const int ar = tid >> 1, ach = (tid & 1) << 1;
    const int br = tid >> 4, bch = (tid & 15) << 1;

    const uint32_t aRowB = (uint32_t)((wr * 64 + ((lane >> 3) & 1) * 8 + (lane & 7)) * (APADH * 2)
                                      + (lane >> 4) * 16);

    auto issue = [&](int kt) {
        const int slot = kt & 3;
        const uint32_t sA = sbase + slot * STAGE_B;
        const uint32_t sB = sA + A_TILE_B;
#pragma unroll
        for (int c = 0; c < 2; c++) {
            cpasync16(sA + (uint32_t)(ar * APADH * 2 + (ach + c) * 16),
                      A + (size_t)(rowBase + ar) * K + kt * 32 + (ach + c) * 8);
            cpasync16(sB + (uint32_t)(br * BPADU * 4 + (bch + c) * 16),
                      Bp32 + (size_t)(kt * 16 + br) * Nu + colBase + (bch + c) * 4);
        }
        CP_COMMIT();
    };

    issue(0); issue(1); issue(2);

    for (int kt = 0; kt < NT; ++kt) {
        asm volatile("cp.async.wait_group 2;");
        __syncthreads();
        if (kt + 3 < NT) issue(kt + 3);
        else CP_COMMIT();

        const uint32_t sAaddr = sbase + (kt & 3) * STAGE_B + aRowB;
        const uint32_t* Bs = (const uint32_t*)(sgm + (kt & 3) * STAGE_B + A_TILE_B);

#pragma unroll
        for (int ks = 0; ks < 2; ++ks) {
            uint32_t af[4][4], bf[4][2];
#pragma unroll
            for (int mi = 0; mi < 4; mi++)
                LDMX4(af[mi][0], af[mi][1], af[mi][2], af[mi][3],
                      sAaddr + (uint32_t)(mi * 16 * (APADH * 2) + ks * 32));
#pragma unroll
            for (int ni = 0; ni < 4; ni++) {
                const uint32_t* bp = Bs + (ks * 8 + tg) * BPADU + wc * 32 + ni * 8 + g;
                bf[ni][0] = bp[0];
                bf[ni][1] = bp[4 * BPADU];
            }
#pragma unroll
            for (int mi = 0; mi < 4; mi++)
#pragma unroll
                for (int ni = 0; ni < 4; ni++)
                    mma_f16(acc[mi][ni], af[mi], bf[ni]);
        }
    }

    if constexpr (!FUSED) {
        // plain epilogue: + bias, fp32 store
#pragma unroll
        for (int mi = 0; mi < 4; mi++) {
            int r0 = rowBase + wr * 64 + mi * 16 + g;
#pragma unroll
            for (int ni = 0; ni < 4; ni++) {
                int c0 = colBase + wc * 32 + ni * 8 + tg * 2;
                float b0 = __ldg(bias + c0), b1 = __ldg(bias + c0 + 1);
                float2 v;
                v.x = acc[mi][ni][0] + b0; v.y = acc[mi][ni][1] + b1;
                *(float2*)(Cmat + (size_t)r0 * N + c0) = v;
                v.x = acc[mi][ni][2] + b0; v.y = acc[mi][ni][3] + b1;
                *(float2*)(Cmat + (size_t)(r0 + 8) * N + c0) = v;
            }
        }
    } else {
        // fused epilogue: stage tile, then RMSNorm+RoPE (q,k) or convert (v)
        __syncthreads();                  // all MMA smem reads done; reuse buffers
        float* stage = (float*)sgm;       // [128][132] fp32 = 67584 B
#pragma unroll
        for (int mi = 0; mi < 4; mi++) {
            int r0 = wr * 64 + mi * 16 + g;
#pragma unroll
            for (int ni = 0; ni < 4; ni++) {
                int cc = wc * 32 + ni * 8 + tg * 2;
                float b0 = __ldg(bias + colBase + cc), b1 = __ldg(bias + colBase + cc + 1);
                stage[r0 * 132 + cc]           = acc[mi][ni][0] + b0;
                stage[r0 * 132 + cc + 1]       = acc[mi][ni][1] + b1;
                stage[(r0 + 8) * 132 + cc]     = acc[mi][ni][2] + b0;
                stage[(r0 + 8) * 132 + cc + 1] = acc[mi][ni][3] + b1;
            }
        }
        __syncthreads();

        const int part = colBase >> 10;       // 0=q, 1=k, 2=v
        const int c0   = colBase & 1023;

        if (part == 2) {
            // v: fp16 convert, coalesced
#pragma unroll
            for (int it = 0; it < 16; ++it) {
                int r = warp * 16 + it;
                const float* row = stage + r * 132;
                size_t o = (size_t)(rowBase + r) * 1024 + c0 + 2 * lane;
                *(__half2*)(vh + o)      = __floats2half2_rn(row[2 * lane], row[2 * lane + 1]);
                *(__half2*)(vh + o + 64) = __floats2half2_rn(row[64 + 2 * lane], row[65 + 2 * lane]);
            }
        } else {
            __half* oh = (part == 0) ? qh : kh;
            __half* ol = (part == 0) ? ql : kl;
            const float* gam = (part == 0) ? gq : gk;
            const float scl = (part == 0) ? 1.0f : 8.0f;   // q folds 1/sqrt(D): 8*0.125=1
            const int j = lane;
            const int h0 = c0 >> 6;
            int axis = (j >= 20) ? 2 : ((j >= 10) ? 1 : 0);
            float freq = exp2f((float)(j - axis * 10) * -1.32877123795494493f);

            for (int it = 0; it < 32; ++it) {
                int unit = warp + 8 * it;          // 0..255 = token*2 + headsub
                int r = unit >> 1, hs = unit & 1;
                float2 t = *(const float2*)(stage + r * 132 + hs * 64 + 2 * j);
                float ss = t.x * t.x + t.y * t.y;
#pragma unroll
                for (int o = 16; o > 0; o >>= 1) ss += __shfl_xor_sync(0xffffffffu, ss, o);
                float inv = scl / fmaxf(sqrtf(ss), 1e-12f);
                float cr = 1.f, sr = 0.f;
                if (j < 30) {
                    float phase = (float)__ldg(coords + (rowBase + r) * 3 + axis) * freq;
                    sincosf(phase, &sr, &cr);
                }
                const float* gp = gam + (h0 + hs) * 64 + 2 * j;
                float v0 = t.x * inv * __ldg(gp);
                float v1 = t.y * inv * __ldg(gp + 1);
                float r0 = v0 * cr - v1 * sr;
                float r1 = v0 * sr + v1 * cr;
                __half hh0 = __float2half_rn(r0), hh1 = __float2half_rn(r1);
                __half2 hv; hv.x = hh0; hv.y = hh1;
                __half2 lv;
                lv.x = __float2half_rn(r0 - __half2float(hh0));
                lv.y = __float2half_rn(r1 - __half2float(hh1));
                size_t o = (size_t)(rowBase + r) * 1024 + c0 + hs * 64 + 2 * j;
                *(__half2*)(oh + o) = hv;
                *(__half2*)(ol + o) = lv;
            }
        }
    }
}

// ---------------- prepasses -------------------------------------------------
__global__ __launch_bounds__(256)
void prep_x_kernel(const float* __restrict__ in, __half* __restrict__ out, int n8)
{
    int i = blockIdx.x * 256 + threadIdx.x;
    int stride = gridDim.x * 256;
    for (; i < n8; i += stride) {
        float4 a = ((const float4*)in)[2 * i];
        float4 b = ((const float4*)in)[2 * i + 1];
        __half2 h[4];
        h[0] = __floats2half2_rn(a.x, a.y);
        h[1] = __floats2half2_rn(a.z, a.w);
        h[2] = __floats2half2_rn(b.x, b.y);
        h[3] = __floats2half2_rn(b.z, b.w);
        ((uint4*)out)[i] = *(uint4*)h;
    }
}

__global__ __launch_bounds__(256)
void prep_w_kernel(const float* __restrict__ W, __half* __restrict__ out, int N, int total4)
{
    int i = blockIdx.x * 256 + threadIdx.x;
    int stride = gridDim.x * 256;
    int n4 = N >> 2;
    for (; i < total4; i += stride) {
        int kp = i / n4, j4 = (i - kp * n4) << 2;
        const float* r0 = W + (size_t)(2 * kp) * N + j4;
        const float* r1 = r0 + N;
        float4 a = *(const float4*)r0;
        float4 b = *(const float4*)r1;
        __half2 h[4];
        h[0] = __floats2half2_rn(a.x, b.x);
        h[1] = __floats2half2_rn(a.y, b.y);
        h[2] = __floats2half2_rn(a.z, b.z);
        h[3] = __floats2half2_rn(a.w, b.w);
        ((uint4*)out)[(size_t)kp * n4 + (j4 >> 2)] = *(uint4*)h;
    }
}

// ---------------- windowed attention (fp16 HMMA, split-compensated) ---------
#define AT_QH 0
#define AT_QL 18432
#define AT_KV 36864
#define AT_KVBUF 55296
#define ATTN_SMEM 147456

__device__ __forceinline__ int win_token(int w, int p) {
    int wx = w >> 4, wy = (w >> 2) & 3, wz = w & 3;
    int px = p >> 6, py = (p >> 3) & 7, pz = p & 7;
    return ((((wx << 3) + px) << 10) | (((wy << 3) + py) << 5) | ((wz << 3) + pz));
}

__global__ __launch_bounds__(256, 1)
void attn_kernel(const __half* __restrict__ qh, const __half* __restrict__ ql,
                 const __half* __restrict__ kh, const __half* __restrict__ kl,
                 const __half* __restrict__ vh,
                 __half* __restrict__ hout)
{
    extern __shared__ __align__(16) char smc[];
    const uint32_t sb = (uint32_t)__cvta_generic_to_shared(smc);
    const int tid  = threadIdx.x;
    const int b    = blockIdx.x;
    const int qc   = b & 3;
    const int head = (b >> 2) & 15;
    const int w    = b >> 6;
    const int lane = tid & 31, wid = tid >> 5;
    const int g = lane >> 2, tg = lane & 3;

    auto cp_tile = [&](const __half* src, uint32_t dstB, int pbase) {
#pragma unroll
        for (int i = 0; i < 4; i++) {
            int c = tid + i * 256;
            int r = c >> 3, seg = c & 7;
            int n = win_token(w, pbase + r);
            cpasync16(sb + dstB + (uint32_t)(r * 144 + seg * 16),
                      src + (size_t)n * 1024 + head * 64 + seg * 8);
        }
    };

    cp_tile(qh, AT_QH, qc * 128);
    cp_tile(ql, AT_QL, qc * 128);
    CP_COMMIT();
    cp_tile(kh, AT_KV, 0);
    cp_tile(kl, AT_KV + 18432, 0);
    cp_tile(vh, AT_KV + 36864, 0);
    CP_COMMIT();

    float oacc[8][4];
#pragma unroll
    for (int t = 0; t < 8; t++)
#pragma unroll
        for (int q = 0; q < 4; q++) oacc[t][q] = 0.f;
    float L0 = 0.f, L1 = 0.f;

    const int qrow = wid * 16 + g;
    const uint32_t* qh_g  = (const uint32_t*)(smc + AT_QH) + qrow * 36;
    const uint32_t* qh_g8 = qh_g + 8 * 36;
    const uint32_t* ql_g  = (const uint32_t*)(smc + AT_QL) + qrow * 36;
    const uint32_t* ql_g8 = ql_g + 8 * 36;

    for (int kt = 0; kt < 4; ++kt) {
        if (kt < 3) {
            uint32_t nb = AT_KV + ((kt + 1) & 1) * AT_KVBUF;
            int pb = (kt + 1) * 128;
            cp_tile(kh, nb, pb);
            cp_tile(kl, nb + 18432, pb);
            cp_tile(vh, nb + 36864, pb);
            CP_COMMIT();
            asm volatile("cp.async.wait_group 1;");
        } else {
            asm volatile("cp.async.wait_group 0;");
        }
        __syncthreads();

        const uint32_t kvB = AT_KV + (kt & 1) * AT_KVBUF;
        const uint32_t* KH32 = (const uint32_t*)(smc + kvB);
        const uint32_t* KL32 = (const uint32_t*)(smc + kvB + 18432);
        const uint32_t VHb = sb + kvB + 36864;

#pragma unroll
        for (int nh = 0; nh < 2; ++nh) {
            float sacc[8][4];
#pragma unroll
            for (int t = 0; t < 8; t++)
#pragma unroll
                for (int q = 0; q < 4; q++) sacc[t][q] = 0.f;

#pragma unroll
            for (int ks = 0; ks < 4; ++ks) {
                const int c0 = tg + 8 * ks, c1 = tg + 4 + 8 * ks;
                uint32_t ah[4], al[4];
                ah[0] = qh_g[c0];  ah[1] = qh_g8[c0];
                ah[2] = qh_g[c1];  ah[3] = qh_g8[c1];
                al[0] = ql_g[c0];  al[1] = ql_g8[c0];
                al[2] = ql_g[c1];  al[3] = ql_g8[c1];
#pragma unroll
                for (int ni = 0; ni < 8; ++ni) {
                    const int krow = nh * 64 + ni * 8 + g;
                    const uint32_t* kro = KH32 + krow * 36;
                    uint32_t bh[2] = { kro[c0], kro[c1] };
                    const uint32_t* krl = KL32 + krow * 36;
                    uint32_t bl[2] = { krl[c0], krl[c1] };
                    mma_f16(sacc[ni], ah, bh);
                    mma_f16(sacc[ni], al, bh);
                    mma_f16(sacc[ni], ah, bl);
                }
            }

            uint32_t ph[8][2];
#pragma unroll
            for (int t = 0; t < 8; t++) {
                float e0 = __expf(sacc[t][0]);
                float e1 = __expf(sacc[t][1]);
                float e2 = __expf(sacc[t][2]);
                float e3 = __expf(sacc[t][3]);
                L0 += e0 + e1;
                L1 += e2 + e3;
                ph[t][0] = packh2(e0, e1);
                ph[t][1] = packh2(e2, e3);
            }

#pragma unroll
            for (int k = 0; k < 4; ++k) {
                uint32_t pA[4] = { ph[2 * k][0], ph[2 * k][1], ph[2 * k + 1][0], ph[2 * k + 1][1] };
                const int keybase = nh * 64 + 16 * k;
                const int tl = lane >> 3;
                const uint32_t rowoff = (uint32_t)((keybase + (lane & 7) + (tl & 1) * 8) * 144
                                                  + (tl >> 1) * 16);
#pragma unroll
                for (int c = 0; c < 4; ++c) {
                    uint32_t ad = rowoff + c * 32;
                    uint32_t r0, r1, r2, r3;
                    LDMX4T(r0, r1, r2, r3, VHb + ad);
                    { uint32_t bb[2] = { r0, r1 }; mma_f16(oacc[2 * c], pA, bb); }
                    { uint32_t bb[2] = { r2, r3 }; mma_f16(oacc[2 * c + 1], pA, bb); }
                }
            }
        }
        __syncthreads();
    }

    L0 += __shfl_xor_sync(0xffffffffu, L0, 1);
    L0 += __shfl_xor_sync(0xffffffffu, L0, 2);
    L1 += __shfl_xor_sync(0xffffffffu, L1, 1);
    L1 += __shfl_xor_sync(0xffffffffu, L1, 2);
    const float inv0 = 1.0f / L0;
    const float inv1 = 1.0f / L1;

    const int q0 = qc * 128 + wid * 16 + g;
    const int n0 = win_token(w, q0);
    const int n1 = win_token(w, q0 + 8);
    __half* o0 = hout + (size_t)n0 * 1024 + head * 64 + 2 * tg;
    __half* o1 = hout + (size_t)n1 * 1024 + head * 64 + 2 * tg;
#pragma unroll
    for (int t = 0; t < 8; t++) {
        __half2 h0 = __floats2half2_rn(oacc[t][0] * inv0, oacc[t][1] * inv0);
        __half2 h1 = __floats2half2_rn(oacc[t][2] * inv1, oacc[t][3] * inv1);
        *(__half2*)(o0 + 8 * t) = h0;
        *(__half2*)(o1 + 8 * t) = h1;
    }
}

// ---------------- launch ----------------------------------------------------
extern "C" void kernel_launch(void* const* d_in, const int* in_sizes, int n_in,
                              void* d_out, int out_size)
{
    const float* x      = (const float*)d_in[0];
    const int*   coords = (const int*)d_in[1];
    const float* Wqkv   = (const float*)d_in[2];
    const float* bqkv   = (const float*)d_in[3];
    const float* gq     = (const float*)d_in[4];
    const float* gk     = (const float*)d_in[5];
    const float* Wout   = (const float*)d_in[6];
    const float* bout   = (const float*)d_in[7];
    float* out = (float*)d_out;

    cudaFuncSetAttribute(gemm_f16_kernel<true>,  cudaFuncAttributeMaxDynamicSharedMemorySize, GEMM_SMEM);
    cudaFuncSetAttribute(gemm_f16_kernel<false>, cudaFuncAttributeMaxDynamicSharedMemorySize, GEMM_SMEM);
    cudaFuncSetAttribute(attn_kernel, cudaFuncAttributeMaxDynamicSharedMemorySize, ATTN_SMEM);

    __half *h16, *x16, *w1p, *w2p, *pqh, *pql, *pkh, *pkl, *pvh;
    cudaGetSymbolAddress((void**)&h16, g_h16);
    cudaGetSymbolAddress((void**)&x16, g_x16);
    cudaGetSymbolAddress((void**)&w1p, g_w1p);
    cudaGetSymbolAddress((void**)&w2p, g_w2p);
    cudaGetSymbolAddress((void**)&pqh, g_qh);
    cudaGetSymbolAddress((void**)&pql, g_ql);
    cudaGetSymbolAddress((void**)&pkh, g_kh);
    cudaGetSymbolAddress((void**)&pkl, g_kl);
    cudaGetSymbolAddress((void**)&pvh, g_vh);

    // prepasses
    prep_x_kernel<<<4096, 256>>>(x, x16, NTOK * CDIM / 8);
    prep_w_kernel<<<4096, 256>>>(Wqkv, w1p, 3 * CDIM, (CDIM / 2) * (3 * CDIM) / 4);
    prep_w_kernel<<<2048, 256>>>(Wout, w2p, CDIM, (CDIM / 2) * CDIM / 4);

    // 1) qkv = x @ Wqkv + bqkv, fused RMSNorm+RoPE+splits in epilogue
    gemm_f16_kernel<true><<<dim3(3072 / 128, NTOK / 128), 256, GEMM_SMEM>>>(
        x16, w1p, bqkv, nullptr, coords, gq, gk,
        pqh, pql, pkh, pkl, pvh, NTOK, 3072, CDIM);

    // 2) windowed attention (fp16 HMMA) -> h fp16
    attn_kernel<<<64 * 16 * 4, 256, ATTN_SMEM>>>(pqh, pql, pkh, pkl, pvh, h16);

    // 3) out = h @ Wout + bout (plain epilogue)
    gemm_f16_kernel<false><<<dim3(1024 / 128, NTOK / 128), 256, GEMM_SMEM>>>(
        h16, w2p, bout, out, nullptr, nullptr, nullptr,
        nullptr, nullptr, nullptr, nullptr, nullptr, NTOK, 1024, CDIM);
}

// round 15
// speedup vs baseline: 1.0124x; 1.0124x over previous
#include <cuda_runtime.h>
#include <cuda_fp16.h>
#include <cstdint>
#include <math.h>

#define NTOK 32768
#define CDIM 1024
#define NHEAD 16
#define HD 64

// ---------------- scratch ---------------------------------------------------
__device__ __half g_h16[NTOK * CDIM];       // attn out fp16
__device__ __half g_x16[NTOK * CDIM];       // x fp16
__device__ __half g_w1p[CDIM * 3 * CDIM];   // Wqkv pair-packed
__device__ __half g_w2p[CDIM * CDIM];       // Wout pair-packed
__device__ float  g_cs[NTOK * 64];          // per-token RoPE cos[32] | sin[32]
// fp16 splits for attention (V has no lo part — linear path, fp16 rounding ok)
__device__ __half g_qh[NTOK * CDIM];
__device__ __half g_ql[NTOK * CDIM];
__device__ __half g_kh[NTOK * CDIM];
__device__ __half g_kl[NTOK * CDIM];
__device__ __half g_vh[NTOK * CDIM];

// ---------------- helpers ---------------------------------------------------
__device__ __forceinline__ void mma_f16(float* d, const uint32_t* a, const uint32_t* b) {
    asm volatile(
        "mma.sync.aligned.m16n8k16.row.col.f32.f16.f16.f32 "
        "{%0,%1,%2,%3}, {%4,%5,%6,%7}, {%8,%9}, {%0,%1,%2,%3};\n"
        : "+f"(d[0]), "+f"(d[1]), "+f"(d[2]), "+f"(d[3])
        : "r"(a[0]), "r"(a[1]), "r"(a[2]), "r"(a[3]), "r"(b[0]), "r"(b[1]));
}

__device__ __forceinline__ void cpasync16(uint32_t dst, const void* src) {
    asm volatile("cp.async.cg.shared.global [%0], [%1], 16;" :: "r"(dst), "l"(src));
}
#define CP_COMMIT() asm volatile("cp.async.commit_group;")

#define LDMX4(r0, r1, r2, r3, addr) \
    asm volatile("ldmatrix.sync.aligned.m8n8.x4.shared.b16 {%0,%1,%2,%3}, [%4];" \
        : "=r"(r0), "=r"(r1), "=r"(r2), "=r"(r3) : "r"(addr))

#define LDMX4T(r0, r1, r2, r3, addr) \
    asm volatile("ldmatrix.sync.aligned.m8n8.x4.trans.shared.b16 {%0,%1,%2,%3}, [%4];" \
        : "=r"(r0), "=r"(r1), "=r"(r2), "=r"(r3) : "r"(addr))

__device__ __forceinline__ uint32_t packh2(float a, float b) {
    __half2 h = __floats2half2_rn(a, b);
    return *(uint32_t*)&h;
}

// ---------------- GEMM (fp16 MMA, 4-stage cp.async, ldmatrix A) -------------
// FUSED=true: epilogue does RMSNorm+RoPE+fp16-splits in place of fp32 store.
#define APADH 40
#define BPADU 136
#define A_TILE_B (128 * APADH * 2)
#define B_TILE_B (16 * BPADU * 4)
#define STAGE_B (A_TILE_B + B_TILE_B)
#define GEMM_SMEM (4 * STAGE_B)

template <bool FUSED>
__global__ __launch_bounds__(256, 2)
void gemm_f16_kernel(const __half* __restrict__ A, const __half* __restrict__ Bp,
                     const float* __restrict__ bias, float* __restrict__ Cmat,
                     const float* __restrict__ cs,
                     const float* __restrict__ gq, const float* __restrict__ gk,
                     __half* __restrict__ qh, __half* __restrict__ ql,
                     __half* __restrict__ kh, __half* __restrict__ kl,
                     __half* __restrict__ vh,
                     int M, int N, int K)
{
    extern __shared__ char sgm[];
    const uint32_t sbase = (uint32_t)__cvta_generic_to_shared(sgm);
    const int tid  = threadIdx.x;
    const int lane = tid & 31, warp = tid >> 5;
    const int g    = lane >> 2, tg = lane & 3;
    const int wr   = warp >> 2, wc = warp & 3;
    const int rowBase = blockIdx.y * 128;
    const int colBase = blockIdx.x * 128;
    const int NT = K >> 5;
    const uint32_t* Bp32 = (const uint32_t*)Bp;
    const int Nu = N;

    float acc[4][4][4];
#pragma unroll
    for (int mi = 0; mi < 4; mi++)
#pragma unroll
        for (int ni = 0; ni < 4; ni++)
#pragma unroll
            for (int q = 0; q < 4; q++) acc[mi][ni][q] = 0.f;

    const int ar = tid >> 1, ach = (tid & 1) << 1;
    const int br = tid >> 4, bch = (tid & 15) << 1;

    const uint32_t aRowB = (uint32_t)((wr * 64 + ((lane >> 3) & 1) * 8 + (lane & 7)) * (APADH * 2)
                                      + (lane >> 4) * 16);

    auto issue = [&](int kt) {
        const int slot = kt & 3;
        const uint32_t sA = sbase + slot * STAGE_B;
        const uint32_t sB = sA + A_TILE_B;
#pragma unroll
        for (int c = 0; c < 2; c++) {
            cpasync16(sA + (uint32_t)(ar * APADH * 2 + (ach + c) * 16),
                      A + (size_t)(rowBase + ar) * K + kt * 32 + (ach + c) * 8);
            cpasync16(sB + (uint32_t)(br * BPADU * 4 + (bch + c) * 16),
                      Bp32 + (size_t)(kt * 16 + br) * Nu + colBase + (bch + c) * 4);
        }
        CP_COMMIT();
    };

    issue(0); issue(1); issue(2);

    for (int kt = 0; kt < NT; ++kt) {
        asm volatile("cp.async.wait_group 2;");
        __syncthreads();
        if (kt + 3 < NT) issue(kt + 3);
        else CP_COMMIT();

        const uint32_t sAaddr = sbase + (kt & 3) * STAGE_B + aRowB;
        const uint32_t* Bs = (const uint32_t*)(sgm + (kt & 3) * STAGE_B + A_TILE_B);

#pragma unroll
        for (int ks = 0; ks < 2; ++ks) {
            uint32_t af[4][4], bf[4][2];
#pragma unroll
            for (int mi = 0; mi < 4; mi++)
                LDMX4(af[mi][0], af[mi][1], af[mi][2], af[mi][3],
                      sAaddr + (uint32_t)(mi * 16 * (APADH * 2) + ks * 32));
#pragma unroll
            for (int ni = 0; ni < 4; ni++) {
                const uint32_t* bp = Bs + (ks * 8 + tg) * BPADU + wc * 32 + ni * 8 + g;
                bf[ni][0] = bp[0];
                bf[ni][1] = bp[4 * BPADU];
            }
#pragma unroll
            for (int mi = 0; mi < 4; mi++)
#pragma unroll
                for (int ni = 0; ni < 4; ni++)
                    mma_f16(acc[mi][ni], af[mi], bf[ni]);
        }
    }

    if constexpr (!FUSED) {
        // plain epilogue: + bias, fp32 store
#pragma unroll
        for (int mi = 0; mi < 4; mi++) {
            int r0 = rowBase + wr * 64 + mi * 16 + g;
#pragma unroll
            for (int ni = 0; ni < 4; ni++) {
                int c0 = colBase + wc * 32 + ni * 8 + tg * 2;
                float b0 = __ldg(bias + c0), b1 = __ldg(bias + c0 + 1);
                float2 v;
                v.x = acc[mi][ni][0] + b0; v.y = acc[mi][ni][1] + b1;
                *(float2*)(Cmat + (size_t)r0 * N + c0) = v;
                v.x = acc[mi][ni][2] + b0; v.y = acc[mi][ni][3] + b1;
                *(float2*)(Cmat + (size_t)(r0 + 8) * N + c0) = v;
            }
        }
    } else {
        // fused epilogue: stage tile, then RMSNorm+RoPE (q,k) or convert (v)
        __syncthreads();                  // all MMA smem reads done; reuse buffers
        float* stage = (float*)sgm;       // [128][132] fp32 = 67584 B
#pragma unroll
        for (int mi = 0; mi < 4; mi++) {
            int r0 = wr * 64 + mi * 16 + g;
#pragma unroll
            for (int ni = 0; ni < 4; ni++) {
                int cc = wc * 32 + ni * 8 + tg * 2;
                float b0 = __ldg(bias + colBase + cc), b1 = __ldg(bias + colBase + cc + 1);
                stage[r0 * 132 + cc]           = acc[mi][ni][0] + b0;
                stage[r0 * 132 + cc + 1]       = acc[mi][ni][1] + b1;
                stage[(r0 + 8) * 132 + cc]     = acc[mi][ni][2] + b0;
                stage[(r0 + 8) * 132 + cc + 1] = acc[mi][ni][3] + b1;
            }
        }
        __syncthreads();

        const int part = colBase >> 10;       // 0=q, 1=k, 2=v
        const int c0   = colBase & 1023;

        if (part == 2) {
            // v: fp16 convert, coalesced
#pragma unroll
            for (int it = 0; it < 16; ++it) {
                int r = warp * 16 + it;
                const float* row = stage + r * 132;
                size_t o = (size_t)(rowBase + r) * 1024 + c0 + 2 * lane;
                *(__half2*)(vh + o)      = __floats2half2_rn(row[2 * lane], row[2 * lane + 1]);
                *(__half2*)(vh + o + 64) = __floats2half2_rn(row[64 + 2 * lane], row[65 + 2 * lane]);
            }
        } else {
            __half* oh = (part == 0) ? qh : kh;
            __half* ol = (part == 0) ? ql : kl;
            const float* gam = (part == 0) ? gq : gk;
            const float scl = (part == 0) ? 1.0f : 8.0f;   // q folds 1/sqrt(D): 8*0.125=1
            const int j = lane;
            const int h0 = c0 >> 6;
            // gamma hoisted: 4 values per lane, fixed for the whole tile
            const float ga0 = __ldg(gam + h0 * 64 + 2 * j);
            const float gb0 = __ldg(gam + h0 * 64 + 2 * j + 1);
            const float ga1 = __ldg(gam + (h0 + 1) * 64 + 2 * j);
            const float gb1 = __ldg(gam + (h0 + 1) * 64 + 2 * j + 1);

            for (int it = 0; it < 32; ++it) {
                int unit = warp + 8 * it;          // 0..255 = token*2 + headsub
                int r = unit >> 1, hs = unit & 1;
                float2 t = *(const float2*)(stage + r * 132 + hs * 64 + 2 * j);
                float ss = t.x * t.x + t.y * t.y;
#pragma unroll
                for (int o = 16; o > 0; o >>= 1) ss += __shfl_xor_sync(0xffffffffu, ss, o);
                float inv = scl / fmaxf(sqrtf(ss), 1e-12f);
                // RoPE cos/sin from precomputed table (L2-resident)
                const float* csp = cs + (size_t)(rowBase + r) * 64;
                float cr = __ldg(csp + j);
                float sr = __ldg(csp + 32 + j);
                float v0 = t.x * inv * (hs ? ga1 : ga0);
                float v1 = t.y * inv * (hs ? gb1 : gb0);
                float r0 = v0 * cr - v1 * sr;
                float r1 = v0 * sr + v1 * cr;
                __half hh0 = __float2half_rn(r0), hh1 = __float2half_rn(r1);
                __half2 hv; hv.x = hh0; hv.y = hh1;
                __half2 lv;
                lv.x = __float2half_rn(r0 - __half2float(hh0));
                lv.y = __float2half_rn(r1 - __half2float(hh1));
                size_t o = (size_t)(rowBase + r) * 1024 + c0 + hs * 64 + 2 * j;
                *(__half2*)(oh + o) = hv;
                *(__half2*)(ol + o) = lv;
            }
        }
    }
}

// ---------------- prepasses -------------------------------------------------
__global__ __launch_bounds__(256)
void prep_x_kernel(const float* __restrict__ in, __half* __restrict__ out, int n8)
{
    int i = blockIdx.x * 256 + threadIdx.x;
    int stride = gridDim.x * 256;
    for (; i < n8; i += stride) {
        float4 a = ((const float4*)in)[2 * i];
        float4 b = ((const float4*)in)[2 * i + 1];
        __half2 h[4];
        h[0] = __floats2half2_rn(a.x, a.y);
        h[1] = __floats2half2_rn(a.z, a.w);
        h[2] = __floats2half2_rn(b.x, b.y);
        h[3] = __floats2half2_rn(b.z, b.w);
        ((uint4*)out)[i] = *(uint4*)h;
    }
}

__global__ __launch_bounds__(256)
void prep_w_kernel(const float* __restrict__ W, __half* __restrict__ out, int N, int total4)
{
    int i = blockIdx.x * 256 + threadIdx.x;
    int stride = gridDim.x * 256;
    int n4 = N >> 2;
    for (; i < total4; i += stride) {
        int kp = i / n4, j4 = (i - kp * n4) << 2;
        const float* r0 = W + (size_t)(2 * kp) * N + j4;
        const float* r1 = r0 + N;
        float4 a = *(const float4*)r0;
        float4 b = *(const float4*)r1;
        __half2 h[4];
        h[0] = __floats2half2_rn(a.x, b.x);
        h[1] = __floats2half2_rn(a.y, b.y);
        h[2] = __floats2half2_rn(a.z, b.z);
        h[3] = __floats2half2_rn(a.w, b.w);
        ((uint4*)out)[(size_t)kp * n4 + (j4 >> 2)] = *(uint4*)h;
    }
}

// per-token RoPE cos/sin table: cs[n*64 + j] = cos_j, cs[n*64 + 32 + j] = sin_j
__global__ __launch_bounds__(256)
void prep_cs_kernel(const int* __restrict__ coords, float* __restrict__ cs)
{
    int n = blockIdx.x * 8 + (threadIdx.x >> 5);
    int j = threadIdx.x & 31;
    float c = 1.f, s = 0.f;
    if (j < 30) {
        int axis = (j >= 20) ? 2 : ((j >= 10) ? 1 : 0);
        int f = j - axis * 10;
        float freq = exp2f((float)f * -1.32877123795494493f);
        float phase = (float)__ldg(coords + n * 3 + axis) * freq;
        sincosf(phase, &s, &c);
    }
    cs[(size_t)n * 64 + j]      = c;
    cs[(size_t)n * 64 + 32 + j] = s;
}

// ---------------- windowed attention (fp16 HMMA, split-compensated) ---------
#define AT_QH 0
#define AT_QL 18432
#define AT_KV 36864
#define AT_KVBUF 55296
#define ATTN_SMEM 147456

__device__ __forceinline__ int win_token(int w, int p) {
    int wx = w >> 4, wy = (w >> 2) & 3, wz = w & 3;
    int px = p >> 6, py = (p >> 3) & 7, pz = p & 7;
    return ((((wx << 3) + px) << 10) | (((wy << 3) + py) << 5) | ((wz << 3) + pz));
}

__global__ __launch_bounds__(256, 1)
void attn_kernel(const __half* __restrict__ qh, const __half* __restrict__ ql,
                 const __half* __restrict__ kh, const __half* __restrict__ kl,
                 const __half* __restrict__ vh,
                 __half* __restrict__ hout)
{
    extern __shared__ __align__(16) char smc[];
    const uint32_t sb = (uint32_t)__cvta_generic_to_shared(smc);
    const int tid  = threadIdx.x;
    const int b    = blockIdx.x;
    const int qc   = b & 3;
    const int head = (b >> 2) & 15;
    const int w    = b >> 6;
    const int lane = tid & 31, wid = tid >> 5;
    const int g = lane >> 2, tg = lane & 3;

    auto cp_tile = [&](const __half* src, uint32_t dstB, int pbase) {
#pragma unroll
        for (int i = 0; i < 4; i++) {
            int c = tid + i * 256;
            int r = c >> 3, seg = c & 7;
            int n = win_token(w, pbase + r);
            cpasync16(sb + dstB + (uint32_t)(r * 144 + seg * 16),
                      src + (size_t)n * 1024 + head * 64 + seg * 8);
        }
    };

    cp_tile(qh, AT_QH, qc * 128);
    cp_tile(ql, AT_QL, qc * 128);
    CP_COMMIT();
    cp_tile(kh, AT_KV, 0);
    cp_tile(kl, AT_KV + 18432, 0);
    cp_tile(vh, AT_KV + 36864, 0);
    CP_COMMIT();

    float oacc[8][4];
#pragma unroll
    for (int t = 0; t < 8; t++)
#pragma unroll
        for (int q = 0; q < 4; q++) oacc[t][q] = 0.f;
    float L0 = 0.f, L1 = 0.f;

    const int qrow = wid * 16 + g;
    const uint32_t* qh_g  = (const uint32_t*)(smc + AT_QH) + qrow * 36;
    const uint32_t* qh_g8 = qh_g + 8 * 36;
    const uint32_t* ql_g  = (const uint32_t*)(smc + AT_QL) + qrow * 36;
    const uint32_t* ql_g8 = ql_g + 8 * 36;

    for (int kt = 0; kt < 4; ++kt) {
        if (kt < 3) {
            uint32_t nb = AT_KV + ((kt + 1) & 1) * AT_KVBUF;
            int pb = (kt + 1) * 128;
            cp_tile(kh, nb, pb);
            cp_tile(kl, nb + 18432, pb);
            cp_tile(vh, nb + 36864, pb);
            CP_COMMIT();
            asm volatile("cp.async.wait_group 1;");
        } else {
            asm volatile("cp.async.wait_group 0;");
        }
        __syncthreads();

        const uint32_t kvB = AT_KV + (kt & 1) * AT_KVBUF;
        const uint32_t* KH32 = (const uint32_t*)(smc + kvB);
        const uint32_t* KL32 = (const uint32_t*)(smc + kvB + 18432);
        const uint32_t VHb = sb + kvB + 36864;

#pragma unroll
        for (int nh = 0; nh < 2; ++nh) {
            float sacc[8][4];
#pragma unroll
            for (int t = 0; t < 8; t++)
#pragma unroll
                for (int q = 0; q < 4; q++) sacc[t][q] = 0.f;

#pragma unroll
            for (int ks = 0; ks < 4; ++ks) {
                const int c0 = tg + 8 * ks, c1 = tg + 4 + 8 * ks;
                uint32_t ah[4], al[4];
                ah[0] = qh_g[c0];  ah[1] = qh_g8[c0];
                ah[2] = qh_g[c1];  ah[3] = qh_g8[c1];
                al[0] = ql_g[c0];  al[1] = ql_g8[c0];
                al[2] = ql_g[c1];  al[3] = ql_g8[c1];
#pragma unroll
                for (int ni = 0; ni < 8; ++ni) {
                    const int krow = nh * 64 + ni * 8 + g;
                    const uint32_t* kro = KH32 + krow * 36;
                    uint32_t bh[2] = { kro[c0], kro[c1] };
                    const uint32_t* krl = KL32 + krow * 36;
                    uint32_t bl[2] = { krl[c0], krl[c1] };
                    mma_f16(sacc[ni], ah, bh);
                    mma_f16(sacc[ni], al, bh);
                    mma_f16(sacc[ni], ah, bl);
                }
            }

            uint32_t ph[8][2];
#pragma unroll
            for (int t = 0; t < 8; t++) {
                float e0 = __expf(sacc[t][0]);
                float e1 = __expf(sacc[t][1]);
                float e2 = __expf(sacc[t][2]);
                float e3 = __expf(sacc[t][3]);
                L0 += e0 + e1;
                L1 += e2 + e3;
                ph[t][0] = packh2(e0, e1);
                ph[t][1] = packh2(e2, e3);
            }

#pragma unroll
            for (int k = 0; k < 4; ++k) {
                uint32_t pA[4] = { ph[2 * k][0], ph[2 * k][1], ph[2 * k + 1][0], ph[2 * k + 1][1] };
                const int keybase = nh * 64 + 16 * k;
                const int tl = lane >> 3;
                const uint32_t rowoff = (uint32_t)((keybase + (lane & 7) + (tl & 1) * 8) * 144
                                                  + (tl >> 1) * 16);
#pragma unroll
                for (int c = 0; c < 4; ++c) {
                    uint32_t ad = rowoff + c * 32;
                    uint32_t r0, r1, r2, r3;
                    LDMX4T(r0, r1, r2, r3, VHb + ad);
                    { uint32_t bb[2] = { r0, r1 }; mma_f16(oacc[2 * c], pA, bb); }
                    { uint32_t bb[2] = { r2, r3 }; mma_f16(oacc[2 * c + 1], pA, bb); }
                }
            }
        }
        __syncthreads();
    }

    L0 += __shfl_xor_sync(0xffffffffu, L0, 1);
    L0 += __shfl_xor_sync(0xffffffffu, L0, 2);
    L1 += __shfl_xor_sync(0xffffffffu, L1, 1);
    L1 += __shfl_xor_sync(0xffffffffu, L1, 2);
    const float inv0 = 1.0f / L0;
    const float inv1 = 1.0f / L1;

    const int q0 = qc * 128 + wid * 16 + g;
    const int n0 = win_token(w, q0);
    const int n1 = win_token(w, q0 + 8);
    __half* o0 = hout + (size_t)n0 * 1024 + head * 64 + 2 * tg;
    __half* o1 = hout + (size_t)n1 * 1024 + head * 64 + 2 * tg;
#pragma unroll
    for (int t = 0; t < 8; t++) {
        __half2 h0 = __floats2half2_rn(oacc[t][0] * inv0, oacc[t][1] * inv0);
        __half2 h1 = __floats2half2_rn(oacc[t][2] * inv1, oacc[t][3] * inv1);
        *(__half2*)(o0 + 8 * t) = h0;
        *(__half2*)(o1 + 8 * t) = h1;
    }
}

// ---------------- launch ----------------------------------------------------
extern "C" void kernel_launch(void* const* d_in, const int* in_sizes, int n_in,
                              void* d_out, int out_size)
{
    const float* x      = (const float*)d_in[0];
    const int*   coords = (const int*)d_in[1];
    const float* Wqkv   = (const float*)d_in[2];
    const float* bqkv   = (const float*)d_in[3];
    const float* gq     = (const float*)d_in[4];
    const float* gk     = (const float*)d_in[5];
    const float* Wout   = (const float*)d_in[6];
    const float* bout   = (const float*)d_in[7];
    float* out = (float*)d_out;

    cudaFuncSetAttribute(gemm_f16_kernel<true>,  cudaFuncAttributeMaxDynamicSharedMemorySize, GEMM_SMEM);
    cudaFuncSetAttribute(gemm_f16_kernel<false>, cudaFuncAttributeMaxDynamicSharedMemorySize, GEMM_SMEM);
    cudaFuncSetAttribute(attn_kernel, cudaFuncAttributeMaxDynamicSharedMemorySize, ATTN_SMEM);

    __half *h16, *x16, *w1p, *w2p, *pqh, *pql, *pkh, *pkl, *pvh;
    float* cs_ptr;
    cudaGetSymbolAddress((void**)&h16, g_h16);
    cudaGetSymbolAddress((void**)&x16, g_x16);
    cudaGetSymbolAddress((void**)&w1p, g_w1p);
    cudaGetSymbolAddress((void**)&w2p, g_w2p);
    cudaGetSymbolAddress((void**)&pqh, g_qh);
    cudaGetSymbolAddress((void**)&pql, g_ql);
    cudaGetSymbolAddress((void**)&pkh, g_kh);
    cudaGetSymbolAddress((void**)&pkl, g_kl);
    cudaGetSymbolAddress((void**)&pvh, g_vh);
    cudaGetSymbolAddress((void**)&cs_ptr, g_cs);

    // prepasses
    prep_cs_kernel<<<NTOK / 8, 256>>>(coords, cs_ptr);
    prep_x_kernel<<<4096, 256>>>(x, x16, NTOK * CDIM / 8);
    prep_w_kernel<<<4096, 256>>>(Wqkv, w1p, 3 * CDIM, (CDIM / 2) * (3 * CDIM) / 4);
    prep_w_kernel<<<2048, 256>>>(Wout, w2p, CDIM, (CDIM / 2) * CDIM / 4);

    // 1) qkv = x @ Wqkv + bqkv, fused RMSNorm+RoPE+splits in epilogue
    gemm_f16_kernel<true><<<dim3(3072 / 128, NTOK / 128), 256, GEMM_SMEM>>>(
        x16, w1p, bqkv, nullptr, cs_ptr, gq, gk,
        pqh, pql, pkh, pkl, pvh, NTOK, 3072, CDIM);

    // 2) windowed attention (fp16 HMMA) -> h fp16
    attn_kernel<<<64 * 16 * 4, 256, ATTN_SMEM>>>(pqh, pql, pkh, pkl, pvh, h16);

    // 3) out = h @ Wout + bout (plain epilogue)
    gemm_f16_kernel<false><<<dim3(1024 / 128, NTOK / 128), 256, GEMM_SMEM>>>(
        h16, w2p, bout, out, nullptr, nullptr, nullptr,
        nullptr, nullptr, nullptr, nullptr, nullptr, NTOK, 1024, CDIM);
}

// round 16
// speedup vs baseline: 1.2349x; 1.2197x over previous
#include <cuda_runtime.h>
#include <cuda_fp16.h>
#include <cstdint>
#include <math.h>

#define NTOK 32768
#define CDIM 1024
#define NHEAD 16
#define HD 64

// ---------------- scratch ---------------------------------------------------
__device__ __half g_h16[NTOK * CDIM];       // attn out fp16
__device__ __half g_x16[NTOK * CDIM];       // x fp16
__device__ __half g_w1p[CDIM * 3 * CDIM];   // Wqkv pair-packed
__device__ __half g_w2p[CDIM * CDIM];       // Wout pair-packed
__device__ float  g_cs[NTOK * 64];          // per-token RoPE cos[32] | sin[32]
// fp16 splits for attention (V has no lo part — linear path, fp16 rounding ok)
__device__ __half g_qh[NTOK * CDIM];
__device__ __half g_ql[NTOK * CDIM];
__device__ __half g_kh[NTOK * CDIM];
__device__ __half g_kl[NTOK * CDIM];
__device__ __half g_vh[NTOK * CDIM];

// ---------------- helpers ---------------------------------------------------
__device__ __forceinline__ void mma_f16(float* d, const uint32_t* a, const uint32_t* b) {
    asm volatile(
        "mma.sync.aligned.m16n8k16.row.col.f32.f16.f16.f32 "
        "{%0,%1,%2,%3}, {%4,%5,%6,%7}, {%8,%9}, {%0,%1,%2,%3};\n"
        : "+f"(d[0]), "+f"(d[1]), "+f"(d[2]), "+f"(d[3])
        : "r"(a[0]), "r"(a[1]), "r"(a[2]), "r"(a[3]), "r"(b[0]), "r"(b[1]));
}

__device__ __forceinline__ void cpasync16(uint32_t dst, const void* src) {
    asm volatile("cp.async.cg.shared.global [%0], [%1], 16;" :: "r"(dst), "l"(src));
}
#define CP_COMMIT() asm volatile("cp.async.commit_group;")

#define LDMX4(r0, r1, r2, r3, addr) \
    asm volatile("ldmatrix.sync.aligned.m8n8.x4.shared.b16 {%0,%1,%2,%3}, [%4];" \
        : "=r"(r0), "=r"(r1), "=r"(r2), "=r"(r3) : "r"(addr))

#define LDMX4T(r0, r1, r2, r3, addr) \
    asm volatile("ldmatrix.sync.aligned.m8n8.x4.trans.shared.b16 {%0,%1,%2,%3}, [%4];" \
        : "=r"(r0), "=r"(r1), "=r"(r2), "=r"(r3) : "r"(addr))

__device__ __forceinline__ uint32_t packh2(float a, float b) {
    __half2 h = __floats2half2_rn(a, b);
    return *(uint32_t*)&h;
}

// ---------------- GEMM (fp16 MMA, K-tile 64, 3-stage cp.async) --------------
// A smem rows: 64 halves data + 8 pad = 144 B (ldmatrix banks 4r mod 32: clean)
// B smem rows: 128 u32 data + 8 pad = 136 u32
#define A_TILE_B 18432            // 128 * 144
#define B_ROW_U 136
#define B_TILE_B 17408            // 32 * 136 * 4
#define STAGE_B (A_TILE_B + B_TILE_B)   // 35840
#define GEMM_SMEM (3 * STAGE_B)          // 107520

template <bool FUSED>
__global__ __launch_bounds__(256, 2)
void gemm_f16_kernel(const __half* __restrict__ A, const __half* __restrict__ Bp,
                     const float* __restrict__ bias, float* __restrict__ Cmat,
                     const float* __restrict__ cs,
                     const float* __restrict__ gq, const float* __restrict__ gk,
                     __half* __restrict__ qh, __half* __restrict__ ql,
                     __half* __restrict__ kh, __half* __restrict__ kl,
                     __half* __restrict__ vh,
                     int M, int N, int K)
{
    extern __shared__ char sgm[];
    const uint32_t sbase = (uint32_t)__cvta_generic_to_shared(sgm);
    const int tid  = threadIdx.x;
    const int lane = tid & 31, warp = tid >> 5;
    const int g    = lane >> 2, tg = lane & 3;
    const int wr   = warp >> 2, wc = warp & 3;
    const int rowBase = blockIdx.y * 128;
    const int colBase = blockIdx.x * 128;
    const int NT = K >> 6;                      // K-tile 64
    const uint32_t* Bp32 = (const uint32_t*)Bp;
    const int Nu = N;

    float acc[4][4][4];
#pragma unroll
    for (int mi = 0; mi < 4; mi++)
#pragma unroll
        for (int ni = 0; ni < 4; ni++)
#pragma unroll
            for (int q = 0; q < 4; q++) acc[mi][ni][q] = 0.f;

    // copy mapping: A 1024 chunks (r=slot>>3, seg=slot&7); B 1024 chunks (row=slot>>5, ch=slot&31)
    const int arr = tid >> 1, asg = (tid & 1) << 2;     // 2 slots/thread base (4 chunks via i)
    const uint32_t aRowB = (uint32_t)((wr * 64 + ((lane >> 3) & 1) * 8 + (lane & 7)) * 144
                                      + (lane >> 4) * 16);

    auto issue = [&](int kt) {
        const int slot = kt % 3;
        const uint32_t sA = sbase + slot * STAGE_B;
        const uint32_t sB = sA + A_TILE_B;
#pragma unroll
        for (int i = 0; i < 4; i++) {
            int s = tid + i * 256;
            int r = s >> 3, seg = s & 7;
            cpasync16(sA + (uint32_t)(r * 144 + seg * 16),
                      A + (size_t)(rowBase + r) * K + kt * 64 + seg * 8);
            int brow = s >> 5, bch = s & 31;
            cpasync16(sB + (uint32_t)(brow * B_ROW_U * 4 + bch * 16),
                      Bp32 + (size_t)(kt * 32 + brow) * Nu + colBase + bch * 4);
        }
        CP_COMMIT();
    };

    issue(0); issue(1);

    for (int kt = 0; kt < NT; ++kt) {
        asm volatile("cp.async.wait_group 1;");
        __syncthreads();            // orders MMA(kt-1) reads before issue below
        if (kt + 2 < NT) issue(kt + 2);
        else CP_COMMIT();

        const uint32_t sAaddr = sbase + (kt % 3) * STAGE_B + aRowB;
        const uint32_t* Bs = (const uint32_t*)(sgm + (kt % 3) * STAGE_B + A_TILE_B);

#pragma unroll
        for (int ks = 0; ks < 4; ++ks) {
            uint32_t af[4][4], bf[4][2];
#pragma unroll
            for (int mi = 0; mi < 4; mi++)
                LDMX4(af[mi][0], af[mi][1], af[mi][2], af[mi][3],
                      sAaddr + (uint32_t)(mi * 16 * 144 + ks * 32));
#pragma unroll
            for (int ni = 0; ni < 4; ni++) {
                const uint32_t* bp = Bs + (ks * 8 + tg) * B_ROW_U + wc * 32 + ni * 8 + g;
                bf[ni][0] = bp[0];
                bf[ni][1] = bp[4 * B_ROW_U];
            }
#pragma unroll
            for (int mi = 0; mi < 4; mi++)
#pragma unroll
                for (int ni = 0; ni < 4; ni++)
                    mma_f16(acc[mi][ni], af[mi], bf[ni]);
        }
    }

    if constexpr (!FUSED) {
#pragma unroll
        for (int mi = 0; mi < 4; mi++) {
            int r0 = rowBase + wr * 64 + mi * 16 + g;
#pragma unroll
            for (int ni = 0; ni < 4; ni++) {
                int c0 = colBase + wc * 32 + ni * 8 + tg * 2;
                float b0 = __ldg(bias + c0), b1 = __ldg(bias + c0 + 1);
                float2 v;
                v.x = acc[mi][ni][0] + b0; v.y = acc[mi][ni][1] + b1;
                *(float2*)(Cmat + (size_t)r0 * N + c0) = v;
                v.x = acc[mi][ni][2] + b0; v.y = acc[mi][ni][3] + b1;
                *(float2*)(Cmat + (size_t)(r0 + 8) * N + c0) = v;
            }
        }
    } else {
        // fused epilogue: stage tile, then RMSNorm+RoPE (q,k) or convert (v)
        __syncthreads();
        float* stage = (float*)sgm;       // [128][132] fp32 = 67584 B
#pragma unroll
        for (int mi = 0; mi < 4; mi++) {
            int r0 = wr * 64 + mi * 16 + g;
#pragma unroll
            for (int ni = 0; ni < 4; ni++) {
                int cc = wc * 32 + ni * 8 + tg * 2;
                float b0 = __ldg(bias + colBase + cc), b1 = __ldg(bias + colBase + cc + 1);
                stage[r0 * 132 + cc]           = acc[mi][ni][0] + b0;
                stage[r0 * 132 + cc + 1]       = acc[mi][ni][1] + b1;
                stage[(r0 + 8) * 132 + cc]     = acc[mi][ni][2] + b0;
                stage[(r0 + 8) * 132 + cc + 1] = acc[mi][ni][3] + b1;
            }
        }
        __syncthreads();

        const int part = colBase >> 10;       // 0=q, 1=k, 2=v
        const int c0   = colBase & 1023;

        if (part == 2) {
#pragma unroll
            for (int it = 0; it < 16; ++it) {
                int r = warp * 16 + it;
                const float* row = stage + r * 132;
                size_t o = (size_t)(rowBase + r) * 1024 + c0 + 2 * lane;
                *(__half2*)(vh + o)      = __floats2half2_rn(row[2 * lane], row[2 * lane + 1]);
                *(__half2*)(vh + o + 64) = __floats2half2_rn(row[64 + 2 * lane], row[65 + 2 * lane]);
            }
        } else {
            __half* oh = (part == 0) ? qh : kh;
            __half* ol = (part == 0) ? ql : kl;
            const float* gam = (part == 0) ? gq : gk;
            const float scl = (part == 0) ? 1.0f : 8.0f;   // q folds 1/sqrt(D)
            const int j = lane;
            const int h0 = c0 >> 6;
            const float ga0 = __ldg(gam + h0 * 64 + 2 * j);
            const float gb0 = __ldg(gam + h0 * 64 + 2 * j + 1);
            const float ga1 = __ldg(gam + (h0 + 1) * 64 + 2 * j);
            const float gb1 = __ldg(gam + (h0 + 1) * 64 + 2 * j + 1);

#pragma unroll 4
            for (int it = 0; it < 32; ++it) {
                int unit = warp + 8 * it;
                int r = unit >> 1, hs = unit & 1;
                float2 t = *(const float2*)(stage + r * 132 + hs * 64 + 2 * j);
                float ss = t.x * t.x + t.y * t.y;
#pragma unroll
                for (int o = 16; o > 0; o >>= 1) ss += __shfl_xor_sync(0xffffffffu, ss, o);
                float inv = scl / fmaxf(sqrtf(ss), 1e-12f);
                const float* csp = cs + (size_t)(rowBase + r) * 64;
                float cr = __ldg(csp + j);
                float sr = __ldg(csp + 32 + j);
                float v0 = t.x * inv * (hs ? ga1 : ga0);
                float v1 = t.y * inv * (hs ? gb1 : gb0);
                float r0 = v0 * cr - v1 * sr;
                float r1 = v0 * sr + v1 * cr;
                __half hh0 = __float2half_rn(r0), hh1 = __float2half_rn(r1);
                __half2 hv; hv.x = hh0; hv.y = hh1;
                __half2 lv;
                lv.x = __float2half_rn(r0 - __half2float(hh0));
                lv.y = __float2half_rn(r1 - __half2float(hh1));
                size_t o = (size_t)(rowBase + r) * 1024 + c0 + hs * 64 + 2 * j;
                *(__half2*)(oh + o) = hv;
                *(__half2*)(ol + o) = lv;
            }
        }
    }
}

// ---------------- prepasses -------------------------------------------------
__global__ __launch_bounds__(256)
void prep_x_kernel(const float* __restrict__ in, __half* __restrict__ out, int n8)
{
    int i = blockIdx.x * 256 + threadIdx.x;
    int stride = gridDim.x * 256;
    for (; i < n8; i += stride) {
        float4 a = ((const float4*)in)[2 * i];
        float4 b = ((const float4*)in)[2 * i + 1];
        __half2 h[4];
        h[0] = __floats2half2_rn(a.x, a.y);
        h[1] = __floats2half2_rn(a.z, a.w);
        h[2] = __floats2half2_rn(b.x, b.y);
        h[3] = __floats2half2_rn(b.z, b.w);
        ((uint4*)out)[i] = *(uint4*)h;
    }
}

__global__ __launch_bounds__(256)
void prep_w_kernel(const float* __restrict__ W, __half* __restrict__ out, int N, int total4)
{
    int i = blockIdx.x * 256 + threadIdx.x;
    int stride = gridDim.x * 256;
    int n4 = N >> 2;
    for (; i < total4; i += stride) {
        int kp = i / n4, j4 = (i - kp * n4) << 2;
        const float* r0 = W + (size_t)(2 * kp) * N + j4;
        const float* r1 = r0 + N;
        float4 a = *(const float4*)r0;
        float4 b = *(const float4*)r1;
        __half2 h[4];
        h[0] = __floats2half2_rn(a.x, b.x);
        h[1] = __floats2half2_rn(a.y, b.y);
        h[2] = __floats2half2_rn(a.z, b.z);
        h[3] = __floats2half2_rn(a.w, b.w);
        ((uint4*)out)[(size_t)kp * n4 + (j4 >> 2)] = *(uint4*)h;
    }
}

// per-token RoPE cos/sin table
__global__ __launch_bounds__(256)
void prep_cs_kernel(const int* __restrict__ coords, float* __restrict__ cs)
{
    int n = blockIdx.x * 8 + (threadIdx.x >> 5);
    int j = threadIdx.x & 31;
    float c = 1.f, s = 0.f;
    if (j < 30) {
        int axis = (j >= 20) ? 2 : ((j >= 10) ? 1 : 0);
        int f = j - axis * 10;
        float freq = exp2f((float)f * -1.32877123795494493f);
        float phase = (float)__ldg(coords + n * 3 + axis) * freq;
        sincosf(phase, &s, &c);
    }
    cs[(size_t)n * 64 + j]      = c;
    cs[(size_t)n * 64 + 32 + j] = s;
}

// ---------------- windowed attention (fp16 HMMA, split-compensated) ---------
#define AT_QH 0
#define AT_QL 18432
#define AT_KV 36864
#define AT_KVBUF 55296
#define ATTN_SMEM 147456

__device__ __forceinline__ int win_token(int w, int p) {
    int wx = w >> 4, wy = (w >> 2) & 3, wz = w & 3;
    int px = p >> 6, py = (p >> 3) & 7, pz = p & 7;
    return ((((wx << 3) + px) << 10) | (((wy << 3) + py) << 5) | ((wz << 3) + pz));
}

__global__ __launch_bounds__(256, 1)
void attn_kernel(const __half* __restrict__ qh, const __half* __restrict__ ql,
                 const __half* __restrict__ kh, const __half* __restrict__ kl,
                 const __half* __restrict__ vh,
                 __half* __restrict__ hout)
{
    extern __shared__ __align__(16) char smc[];
    const uint32_t sb = (uint32_t)__cvta_generic_to_shared(smc);
    const int tid  = threadIdx.x;
    const int b    = blockIdx.x;
    const int qc   = b & 3;
    const int head = (b >> 2) & 15;
    const int w    = b >> 6;
    const int lane = tid & 31, wid = tid >> 5;
    const int g = lane >> 2, tg = lane & 3;

    auto cp_tile = [&](const __half* src, uint32_t dstB, int pbase) {
#pragma unroll
        for (int i = 0; i < 4; i++) {
            int c = tid + i * 256;
            int r = c >> 3, seg = c & 7;
            int n = win_token(w, pbase + r);
            cpasync16(sb + dstB + (uint32_t)(r * 144 + seg * 16),
                      src + (size_t)n * 1024 + head * 64 + seg * 8);
        }
    };

    cp_tile(qh, AT_QH, qc * 128);
    cp_tile(ql, AT_QL, qc * 128);
    CP_COMMIT();
    cp_tile(kh, AT_KV, 0);
    cp_tile(kl, AT_KV + 18432, 0);
    cp_tile(vh, AT_KV + 36864, 0);
    CP_COMMIT();

    float oacc[8][4];
#pragma unroll
    for (int t = 0; t < 8; t++)
#pragma unroll
        for (int q = 0; q < 4; q++) oacc[t][q] = 0.f;
    float L0 = 0.f, L1 = 0.f;

    const int qrow = wid * 16 + g;
    const uint32_t* qh_g  = (const uint32_t*)(smc + AT_QH) + qrow * 36;
    const uint32_t* qh_g8 = qh_g + 8 * 36;
    const uint32_t* ql_g  = (const uint32_t*)(smc + AT_QL) + qrow * 36;
    const uint32_t* ql_g8 = ql_g + 8 * 36;

    for (int kt = 0; kt < 4; ++kt) {
        if (kt < 3) {
            uint32_t nb = AT_KV + ((kt + 1) & 1) * AT_KVBUF;
            int pb = (kt + 1) * 128;
            cp_tile(kh, nb, pb);
            cp_tile(kl, nb + 18432, pb);
            cp_tile(vh, nb + 36864, pb);
            CP_COMMIT();
            asm volatile("cp.async.wait_group 1;");
        } else {
            asm volatile("cp.async.wait_group 0;");
        }
        __syncthreads();

        const uint32_t kvB = AT_KV + (kt & 1) * AT_KVBUF;
        const uint32_t* KH32 = (const uint32_t*)(smc + kvB);
        const uint32_t* KL32 = (const uint32_t*)(smc + kvB + 18432);
        const uint32_t VHb = sb + kvB + 36864;

#pragma unroll
        for (int nh = 0; nh < 2; ++nh) {
            float sacc[8][4];
#pragma unroll
            for (int t = 0; t < 8; t++)
#pragma unroll
                for (int q = 0; q < 4; q++) sacc[t][q] = 0.f;

#pragma unroll
            for (int ks = 0; ks < 4; ++ks) {
                const int c0 = tg + 8 * ks, c1 = tg + 4 + 8 * ks;
                uint32_t ah[4], al[4];
                ah[0] = qh_g[c0];  ah[1] = qh_g8[c0];
                ah[2] = qh_g[c1];  ah[3] = qh_g8[c1];
                al[0] = ql_g[c0];  al[1] = ql_g8[c0];
                al[2] = ql_g[c1];  al[3] = ql_g8[c1];
#pragma unroll
                for (int ni = 0; ni < 8; ++ni) {
                    const int krow = nh * 64 + ni * 8 + g;
                    const uint32_t* kro = KH32 + krow * 36;
                    uint32_t bh[2] = { kro[c0], kro[c1] };
                    const uint32_t* krl = KL32 + krow * 36;
                    uint32_t bl[2] = { krl[c0], krl[c1] };
                    mma_f16(sacc[ni], ah, bh);
                    mma_f16(sacc[ni], al, bh);
                    mma_f16(sacc[ni], ah, bl);
                }
            }

            uint32_t ph[8][2];
#pragma unroll
            for (int t = 0; t < 8; t++) {
                float e0 = __expf(sacc[t][0]);
                float e1 = __expf(sacc[t][1]);
                float e2 = __expf(sacc[t][2]);
                float e3 = __expf(sacc[t][3]);
                L0 += e0 + e1;
                L1 += e2 + e3;
                ph[t][0] = packh2(e0, e1);
                ph[t][1] = packh2(e2, e3);
            }

#pragma unroll
            for (int k = 0; k < 4; ++k) {
                uint32_t pA[4] = { ph[2 * k][0], ph[2 * k][1], ph[2 * k + 1][0], ph[2 * k + 1][1] };
                const int keybase = nh * 64 + 16 * k;
                const int tl = lane >> 3;
                const uint32_t rowoff = (uint32_t)((keybase + (lane & 7) + (tl & 1) * 8) * 144
                                                  + (tl >> 1) * 16);
#pragma unroll
                for (int c = 0; c < 4; ++c) {
                    uint32_t ad = rowoff + c * 32;
                    uint32_t r0, r1, r2, r3;
                    LDMX4T(r0, r1, r2, r3, VHb + ad);
                    { uint32_t bb[2] = { r0, r1 }; mma_f16(oacc[2 * c], pA, bb); }
                    { uint32_t bb[2] = { r2, r3 }; mma_f16(oacc[2 * c + 1], pA, bb); }
                }
            }
        }
        __syncthreads();
    }

    L0 += __shfl_xor_sync(0xffffffffu, L0, 1);
    L0 += __shfl_xor_sync(0xffffffffu, L0, 2);
    L1 += __shfl_xor_sync(0xffffffffu, L1, 1);
    L1 += __shfl_xor_sync(0xffffffffu, L1, 2);
    const float inv0 = 1.0f / L0;
    const float inv1 = 1.0f / L1;

    const int q0 = qc * 128 + wid * 16 + g;
    const int n0 = win_token(w, q0);
    const int n1 = win_token(w, q0 + 8);
    __half* o0 = hout + (size_t)n0 * 1024 + head * 64 + 2 * tg;
    __half* o1 = hout + (size_t)n1 * 1024 + head * 64 + 2 * tg;
#pragma unroll
    for (int t = 0; t < 8; t++) {
        __half2 h0 = __floats2half2_rn(oacc[t][0] * inv0, oacc[t][1] * inv0);
        __half2 h1 = __floats2half2_rn(oacc[t][2] * inv1, oacc[t][3] * inv1);
        *(__half2*)(o0 + 8 * t) = h0;
        *(__half2*)(o1 + 8 * t) = h1;
    }
}

// ---------------- launch ----------------------------------------------------
extern "C" void kernel_launch(void* const* d_in, const int* in_sizes, int n_in,
                              void* d_out, int out_size)
{
    const float* x      = (const float*)d_in[0];
    const int*   coords = (const int*)d_in[1];
    const float* Wqkv   = (const float*)d_in[2];
    const float* bqkv   = (const float*)d_in[3];
    const float* gq     = (const float*)d_in[4];
    const float* gk     = (const float*)d_in[5];
    const float* Wout   = (const float*)d_in[6];
    const float* bout   = (const float*)d_in[7];
    float* out = (float*)d_out;

    cudaFuncSetAttribute(gemm_f16_kernel<true>,  cudaFuncAttributeMaxDynamicSharedMemorySize, GEMM_SMEM);
    cudaFuncSetAttribute(gemm_f16_kernel<false>, cudaFuncAttributeMaxDynamicSharedMemorySize, GEMM_SMEM);
    cudaFuncSetAttribute(attn_kernel, cudaFuncAttributeMaxDynamicSharedMemorySize, ATTN_SMEM);

    __half *h16, *x16, *w1p, *w2p, *pqh, *pql, *pkh, *pkl, *pvh;
    float* cs_ptr;
    cudaGetSymbolAddress((void**)&h16, g_h16);
    cudaGetSymbolAddress((void**)&x16, g_x16);
    cudaGetSymbolAddress((void**)&w1p, g_w1p);
    cudaGetSymbolAddress((void**)&w2p, g_w2p);
    cudaGetSymbolAddress((void**)&pqh, g_qh);
    cudaGetSymbolAddress((void**)&pql, g_ql);
    cudaGetSymbolAddress((void**)&pkh, g_kh);
    cudaGetSymbolAddress((void**)&pkl, g_kl);
    cudaGetSymbolAddress((void**)&pvh, g_vh);
    cudaGetSymbolAddress((void**)&cs_ptr, g_cs);

    // prepasses
    prep_cs_kernel<<<NTOK / 8, 256>>>(coords, cs_ptr);
    prep_x_kernel<<<4096, 256>>>(x, x16, NTOK * CDIM / 8);
    prep_w_kernel<<<4096, 256>>>(Wqkv, w1p, 3 * CDIM, (CDIM / 2) * (3 * CDIM) / 4);
    prep_w_kernel<<<2048, 256>>>(Wout, w2p, CDIM, (CDIM / 2) * CDIM / 4);

    // 1) qkv = x @ Wqkv + bqkv, fused RMSNorm+RoPE+splits in epilogue
    gemm_f16_kernel<true><<<dim3(3072 / 128, NTOK / 128), 256, GEMM_SMEM>>>(
        x16, w1p, bqkv, nullptr, cs_ptr, gq, gk,
        pqh, pql, pkh, pkl, pvh, NTOK, 3072, CDIM);

    // 2) windowed attention (fp16 HMMA) -> h fp16
    attn_kernel<<<64 * 16 * 4, 256, ATTN_SMEM>>>(pqh, pql, pkh, pkl, pvh, h16);

    // 3) out = h @ Wout + bout (plain epilogue)
    gemm_f16_kernel<false><<<dim3(1024 / 128, NTOK / 128), 256, GEMM_SMEM>>>(
        h16, w2p, bout, out, nullptr, nullptr, nullptr,
        nullptr, nullptr, nullptr, nullptr, nullptr, NTOK, 1024, CDIM);
}